// round 5
// baseline (speedup 1.0000x reference)
#include <cuda_runtime.h>
#include <cuda_bf16.h>
#include <cstdint>
#include <math.h>

// ---------------- sizes ----------------
#define BATCH   4096
#define EDIM    128
#define KIH     7808
#define KDIM    7936            // KIH + 128 (h0 folded in)
#define NGATES  512
#define LHID    128
#define HDIM    64
#define NCHUNK  (KDIM/32)       // 248 k-chunks of 32 floats

// ---------------- device scratch (static: no allocs allowed) ----------------
__device__ __align__(1024) float g_x[(size_t)BATCH * KDIM];    // ~130 MB
__device__ __align__(1024) float g_W[(size_t)NGATES * KDIM];   // ~16 MB
__device__ float g_bias[NGATES];
__device__ float g_h1[(size_t)BATCH * LHID];                   // fallback homes
__device__ float g_c1[(size_t)BATCH * LHID];

// ---------------- helpers ----------------
__device__ __forceinline__ uint32_t smem_to_u32(const void* p) {
    uint32_t a;
    asm("{ .reg .u64 t; cvta.to.shared.u64 t, %1; cvt.u32.u64 %0, t; }" : "=r"(a) : "l"(p));
    return a;
}
__device__ __forceinline__ float tf32r(float x) {
    uint32_t u;
    asm("cvt.rna.tf32.f32 %0, %1;" : "=r"(u) : "f"(x));
    return __uint_as_float(u);
}
#define CP_ASYNC16(sm_u32, gptr) \
    asm volatile("cp.async.cg.shared.global [%0], [%1], 16;" :: "r"(sm_u32), "l"(gptr))
#define CP_COMMIT() asm volatile("cp.async.commit_group;")
#define CP_WAIT(n)  asm volatile("cp.async.wait_group %0;" :: "n"(n))

#define LDMX4(r0, r1, r2, r3, addr) \
    asm volatile("ldmatrix.sync.aligned.m8n8.x4.shared.b16 {%0,%1,%2,%3}, [%4];" \
                 : "=r"(r0), "=r"(r1), "=r"(r2), "=r"(r3) : "r"(addr))

#define MMA_TF32(d, a, b0, b1) \
    asm volatile("mma.sync.aligned.m16n8k8.row.col.f32.tf32.tf32.f32 " \
                 "{%0,%1,%2,%3}, {%4,%5,%6,%7}, {%8,%9}, {%0,%1,%2,%3};" \
                 : "+f"((d)[0]), "+f"((d)[1]), "+f"((d)[2]), "+f"((d)[3]) \
                 : "r"((a)[0]), "r"((a)[1]), "r"((a)[2]), "r"((a)[3]), \
                   "r"(b0), "r"(b1))

// =====================================================================
// K1: permute + pack W = [Wih | Whh], row p = 4h+gate (gate order i,f,g,o)
// =====================================================================
__global__ void prep_w_kernel(const float* __restrict__ Wih, const float* __restrict__ Whh,
                              const float* __restrict__ bih, const float* __restrict__ bhh) {
    const int p = blockIdx.y;
    const int col = blockIdx.x * 256 + threadIdx.x;   // 0..7935
    const int h = p >> 2, gate = p & 3;
    const int orig = gate * LHID + h;
    float v = (col < KIH) ? Wih[(size_t)orig * KIH + col]
                          : Whh[(size_t)orig * LHID + (col - KIH)];
    g_W[(size_t)p * KDIM + col] = tf32r(v);
    if (blockIdx.x == 0 && threadIdx.x == 0)
        g_bias[p] = bih[orig] + bhh[orig];
}

// =====================================================================
// K2: numerical projection -> g_x cols [7680,7808), num_W cached in smem
// =====================================================================
#define NUM_SMEM ((32*84 + 128*85) * 4)
__global__ void num_kernel(const float* __restrict__ numerical,
                           const float* __restrict__ num_W, const float* __restrict__ num_b) {
    extern __shared__ float sm[];
    float* snum = sm;                  // [32][84]
    float* sW = sm + 32 * 84;          // [128][85] padded
    const int t = threadIdx.x;
    const int b0 = blockIdx.x * 32;
    for (int i = t; i < 32 * 84; i += 128)
        snum[i] = numerical[(size_t)b0 * 84 + i];
    for (int i = t; i < 128 * 84; i += 128) {
        int e = i / 84, k = i - e * 84;
        sW[e * 85 + k] = num_W[i];
    }
    __syncthreads();
    const int e = t; // 0..127
    float bb = num_b[e];
    for (int r = 0; r < 32; r++) {
        float acc = bb;
        #pragma unroll 4
        for (int k = 0; k < 84; k++)
            acc += snum[r * 84 + k] * sW[e * 85 + k];
        g_x[(size_t)(b0 + r) * KDIM + 7680 + e] = tf32r(acc);
    }
}

// =====================================================================
// K3: gather-build x rows: [12*128 ab | 48*128 mv | 128 num(skip) | 128 h0]
// =====================================================================
__global__ void build_x_kernel(const int* __restrict__ aid_g, const int* __restrict__ mid_g,
                               const float* __restrict__ aemb, const float* __restrict__ memb,
                               const float* __restrict__ h0) {
    const int b = blockIdx.x;
    const int* aid = aid_g + b * 12;
    const int* mid = mid_g + b * 48;
    float4* dst = ((float4*)g_x) + (size_t)b * (KDIM / 4);
    for (int c = threadIdx.x; c < 1952; c += blockDim.x) {
        const float4* src;
        int dc;
        if (c < 384) {                       // ability: 12 segs x 32 f4
            int j = c >> 5, e4 = c & 31;
            src = ((const float4*)(aemb + (size_t)aid[j] * EDIM)) + e4;
            dc = c;
        } else if (c < 1920) {               // moves: 48 segs x 32 f4
            int cm = c - 384;
            int j = cm >> 5, e4 = cm & 31;
            src = ((const float4*)(memb + (size_t)mid[j] * EDIM)) + e4;
            dc = c;
        } else {                             // h0 -> cols [7808,7936)
            int e4 = c - 1920;
            src = ((const float4*)(h0 + (size_t)b * LHID)) + e4;
            dc = c + 32;                     // skip num region (32 f4)
        }
        float4 v = *src;
        v.x = tf32r(v.x); v.y = tf32r(v.y); v.z = tf32r(v.z); v.w = tf32r(v.w);
        dst[dc] = v;
    }
}

// =====================================================================
// K4: tf32 mma.sync GEMM (4096x512x7936) + fused LSTM cell epilogue
// grid (4 nt, 32 mt), 128 threads = 4 warps, each warp a 64x64 quadrant.
// 3-stage cp.async pipeline. Smem row pitch 36 floats (144B): ldmatrix
// rows land in disjoint bank groups (36r mod 32 = 4r) -> conflict-free.
// =====================================================================
#define APITCH_F 36
#define APITCH_B 144
#define ATILE_B  (128 * APITCH_B)          // 18432 bytes per operand tile
#define STAGE_B  (2 * ATILE_B)             // 36864: A tile then B tile
#define NSTG     3
#define GEMM_SMEM (NSTG * STAGE_B)         // 110592 bytes
#define GPITCH_F 132                       // gates staging pitch

__device__ __forceinline__ void load_stage(int s, int kc, int mt, int nt,
                                           int tid, uint32_t sbase) {
    const float* ga = g_x + (size_t)(mt * 128) * KDIM + kc * 32;
    const float* gb = g_W + (size_t)(nt * 128) * KDIM + kc * 32;
    const uint32_t sa = sbase + s * STAGE_B;
    const uint32_t sb2 = sa + ATILE_B;
    #pragma unroll
    for (int i = 0; i < 8; i++) {
        int g = tid + i * 128;             // 0..1023 granules of 16B
        int row = g >> 3, c = g & 7;
        CP_ASYNC16(sa  + row * APITCH_B + c * 16, ga + (size_t)row * KDIM + c * 4);
        CP_ASYNC16(sb2 + row * APITCH_B + c * 16, gb + (size_t)row * KDIM + c * 4);
    }
    CP_COMMIT();
}

__global__ void __launch_bounds__(128, 1)
gemm_lstm_kernel(const float* __restrict__ c0,
                 float* __restrict__ out_h1, float* __restrict__ out_c1) {
    extern __shared__ char smem[];
    const uint32_t sbase = smem_to_u32(smem);
    const int tid = threadIdx.x, lane = tid & 31, wid = tid >> 5;
    const int nt = blockIdx.x, mt = blockIdx.y;
    const int warpM = (wid >> 1) * 64;     // 0 or 64
    const int warpN = (wid & 1) * 64;      // 0 or 64

    float acc[4][8][4];
    #pragma unroll
    for (int i = 0; i < 4; i++)
        #pragma unroll
        for (int n = 0; n < 8; n++)
            #pragma unroll
            for (int q = 0; q < 4; q++) acc[i][n][q] = 0.0f;

    // per-thread ldmatrix base (within A tile): sub-matrix role of this lane
    const int sub = lane >> 3, rr = lane & 7;
    const uint32_t a_base_off =
        (uint32_t)(warpM + ((sub & 1) << 3) + rr) * APITCH_B + ((sub >> 1) << 4);
    // per-thread B base (float index within B tile)
    const int b_base = (warpN + (lane >> 2)) * APITCH_F + (lane & 3);

    load_stage(0, 0, mt, nt, tid, sbase);
    load_stage(1, 1, mt, nt, tid, sbase);

    for (int kc = 0; kc < NCHUNK; kc++) {
        CP_WAIT(1);
        __syncthreads();
        if (kc + 2 < NCHUNK)
            load_stage((kc + 2) % NSTG, kc + 2, mt, nt, tid, sbase);

        const int st = kc % NSTG;
        const uint32_t a0 = sbase + st * STAGE_B + a_base_off;
        const float* bs = (const float*)(smem + st * STAGE_B + ATILE_B) + b_base;

        #pragma unroll
        for (int j = 0; j < 4; j++) {      // k-steps of 8 within the 32-chunk
            uint32_t af[4][4];
            #pragma unroll
            for (int i = 0; i < 4; i++)
                LDMX4(af[i][0], af[i][1], af[i][2], af[i][3],
                      a0 + i * 16 * APITCH_B + j * 32);
            uint32_t bf0[8], bf1[8];
            #pragma unroll
            for (int n = 0; n < 8; n++) {
                bf0[n] = __float_as_uint(bs[n * 8 * APITCH_F + j * 8]);
                bf1[n] = __float_as_uint(bs[n * 8 * APITCH_F + j * 8 + 4]);
            }
            #pragma unroll
            for (int i = 0; i < 4; i++)
                #pragma unroll
                for (int n = 0; n < 8; n++)
                    MMA_TF32(acc[i][n], af[i], bf0[n], bf1[n]);
        }
    }
    CP_WAIT(0);
    __syncthreads();

    // ---- stage gates through smem so each thread gets full i,f,g,o ----
    float* sg = (float*)smem;              // [128][GPITCH_F]
    {
        const int r0 = lane >> 2, c0i = 2 * (lane & 3);
        #pragma unroll
        for (int i = 0; i < 4; i++)
            #pragma unroll
            for (int n = 0; n < 8; n++) {
                const int row = warpM + 16 * i + r0;
                const int col = warpN + 8 * n + c0i;
                sg[row * GPITCH_F + col]           = acc[i][n][0];
                sg[row * GPITCH_F + col + 1]       = acc[i][n][1];
                sg[(row + 8) * GPITCH_F + col]     = acc[i][n][2];
                sg[(row + 8) * GPITCH_F + col + 1] = acc[i][n][3];
            }
    }
    __syncthreads();

    // ---- fused LSTM cell: thread tid owns batch row m = mt*128+tid ----
    {
        const int m = mt * 128 + tid;
        const float* c0row = c0 + (size_t)m * LHID;
        float* h1row = out_h1 + (size_t)m * LHID;
        float* c1row = out_c1 + (size_t)m * LHID;
        const float* grow = sg + tid * GPITCH_F;
        #pragma unroll 4
        for (int hl = 0; hl < 32; hl++) {
            const int pb = nt * 128 + 4 * hl;
            float gi = grow[4 * hl + 0] + g_bias[pb + 0];
            float gf = grow[4 * hl + 1] + g_bias[pb + 1];
            float gg = grow[4 * hl + 2] + g_bias[pb + 2];
            float go = grow[4 * hl + 3] + g_bias[pb + 3];
            float iv = 1.0f / (1.0f + expf(-gi));
            float fv = 1.0f / (1.0f + expf(-gf));
            float gv = tanhf(gg);
            float ov = 1.0f / (1.0f + expf(-go));
            const int h = nt * 32 + hl;
            float c1 = fv * c0row[h] + iv * gv;
            float h1 = ov * tanhf(c1);
            h1row[h] = h1;
            c1row[h] = c1;
        }
    }
}

// =====================================================================
// K5: MLP head + softmax + masked renorm. 16 rows/block, 256 threads.
// =====================================================================
#define W1S 132
#define W2S 68
#define WAS 132
#define H1S 132
#define FTS 132
#define OW1 0
#define OW2 (OW1 + 64 * W1S)
#define OWA (OW2 + 128 * W2S)
#define OB1 (OWA + 9 * WAS)
#define OB2 (OB1 + 64)
#define OBA (OB2 + 128)
#define OH1 (OBA + 12)
#define OZ1 (OH1 + 16 * H1S)
#define OFT (OZ1 + 16 * 64)
#define HEAD_FLOATS (OFT + 16 * FTS)
#define HEAD_SMEM (HEAD_FLOATS * 4)

__global__ void head_kernel(const float* __restrict__ h1g, const float* __restrict__ mask,
                            const float* __restrict__ W1, const float* __restrict__ b1,
                            const float* __restrict__ W2, const float* __restrict__ b2,
                            const float* __restrict__ Wa, const float* __restrict__ ba,
                            float* __restrict__ probs) {
    extern __shared__ float sm[];
    const int t = threadIdx.x;
    const int b0 = blockIdx.x * 16;

    for (int i = t; i < 64 * 128; i += 256) { int r = i >> 7, k = i & 127; sm[OW1 + r * W1S + k] = W1[i]; }
    for (int i = t; i < 128 * 64; i += 256) { int r = i >> 6, k = i & 63;  sm[OW2 + r * W2S + k] = W2[i]; }
    for (int i = t; i < 9 * 128;  i += 256) { int r = i >> 7, k = i & 127; sm[OWA + r * WAS + k] = Wa[i]; }
    if (t < 64)  sm[OB1 + t] = b1[t];
    if (t < 128) sm[OB2 + t] = b2[t];
    if (t < 9)   sm[OBA + t] = ba[t];
    for (int i = t; i < 16 * 128; i += 256) { int r = i >> 7, k = i & 127; sm[OH1 + r * H1S + k] = h1g[(size_t)(b0 + r) * LHID + k]; }
    __syncthreads();

    for (int oi = t; oi < 16 * 64; oi += 256) {
        int r = oi >> 6, j = oi & 63;
        float acc = sm[OB1 + j];
        #pragma unroll 8
        for (int k = 0; k < 32; k++) {
            float4 a = *(const float4*)&sm[OH1 + r * H1S + 4 * k];
            float4 w = *(const float4*)&sm[OW1 + j * W1S + 4 * k];
            acc += a.x * w.x + a.y * w.y + a.z * w.z + a.w * w.w;
        }
        sm[OZ1 + r * 64 + j] = fmaxf(acc, 0.0f);
    }
    __syncthreads();

    for (int oi = t; oi < 16 * 128; oi += 256) {
        int r = oi >> 7, e = oi & 127;
        float acc = sm[OB2 + e];
        #pragma unroll 8
        for (int k = 0; k < 16; k++) {
            float4 a = *(const float4*)&sm[OZ1 + r * 64 + 4 * k];
            float4 w = *(const float4*)&sm[OW2 + e * W2S + 4 * k];
            acc += a.x * w.x + a.y * w.y + a.z * w.z + a.w * w.w;
        }
        sm[OFT + r * FTS + e] = acc;
    }
    __syncthreads();

    if (t < 16) {
        const int r = t, b = b0 + r;
        float lg[9];
        #pragma unroll
        for (int j = 0; j < 9; j++) {
            float acc = sm[OBA + j];
            #pragma unroll 8
            for (int k = 0; k < 32; k++) {
                float4 a = *(const float4*)&sm[OFT + r * FTS + 4 * k];
                float4 w = *(const float4*)&sm[OWA + j * WAS + 4 * k];
                acc += a.x * w.x + a.y * w.y + a.z * w.z + a.w * w.w;
            }
            lg[j] = acc;
        }
        float mx = lg[0];
        #pragma unroll
        for (int j = 1; j < 9; j++) mx = fmaxf(mx, lg[j]);
        float ex[9], se = 0.0f;
        #pragma unroll
        for (int j = 0; j < 9; j++) { ex[j] = expf(lg[j] - mx); se += ex[j]; }
        float inv = 1.0f / se;
        float p[9], mk[9], ms = 0.0f;
        #pragma unroll
        for (int j = 0; j < 9; j++) {
            p[j] = ex[j] * inv;
            mk[j] = mask[(size_t)b * 9 + j];
            ms += p[j] * mk[j];
        }
        if (ms > 0.0f) {
            float mi = 1.0f / ms;
            #pragma unroll
            for (int j = 0; j < 9; j++) probs[(size_t)b * 9 + j] = p[j] * mk[j] * mi;
        } else {
            #pragma unroll
            for (int j = 0; j < 9; j++) probs[(size_t)b * 9 + j] = p[j];
        }
    }
}

// =====================================================================
// launcher
// =====================================================================
extern "C" void kernel_launch(void* const* d_in, const int* in_sizes, int n_in,
                              void* d_out, int out_size) {
    const int*   ability_ids = (const int*)d_in[0];
    const int*   move_ids    = (const int*)d_in[1];
    const float* numerical   = (const float*)d_in[2];
    const float* mask        = (const float*)d_in[3];
    const float* h0          = (const float*)d_in[4];
    const float* c0          = (const float*)d_in[5];
    const float* ability_emb = (const float*)d_in[6];
    const float* move_emb    = (const float*)d_in[7];
    const float* num_W       = (const float*)d_in[8];
    const float* num_b       = (const float*)d_in[9];
    const float* Wih         = (const float*)d_in[10];
    const float* Whh         = (const float*)d_in[11];
    const float* bih         = (const float*)d_in[12];
    const float* bhh         = (const float*)d_in[13];
    const float* W1          = (const float*)d_in[14];
    const float* b1          = (const float*)d_in[15];
    const float* W2          = (const float*)d_in[16];
    const float* b2          = (const float*)d_in[17];
    const float* Wa          = (const float*)d_in[18];
    const float* ba          = (const float*)d_in[19];

    float* out   = (float*)d_out;
    float* probs = out;

    // defensive output routing: tuple (probs, h1, c1) expected; fall back to
    // scratch for h1/c1 if d_out is smaller than the full tuple.
    const long long full = (long long)BATCH * 9 + 2LL * BATCH * LHID;
    void *ph1s = nullptr, *pc1s = nullptr;
    cudaGetSymbolAddress(&ph1s, g_h1);
    cudaGetSymbolAddress(&pc1s, g_c1);
    float* h1o = (out_size >= full) ? out + (size_t)BATCH * 9 : (float*)ph1s;
    float* c1o = (out_size >= full) ? h1o + (size_t)BATCH * LHID : (float*)pc1s;

    cudaFuncSetAttribute(gemm_lstm_kernel, cudaFuncAttributeMaxDynamicSharedMemorySize, GEMM_SMEM);
    cudaFuncSetAttribute(num_kernel,       cudaFuncAttributeMaxDynamicSharedMemorySize, NUM_SMEM);
    cudaFuncSetAttribute(head_kernel,      cudaFuncAttributeMaxDynamicSharedMemorySize, HEAD_SMEM);

    prep_w_kernel<<<dim3(KDIM / 256, NGATES), 256>>>(Wih, Whh, bih, bhh);
    num_kernel<<<BATCH / 32, 128, NUM_SMEM>>>(numerical, num_W, num_b);
    build_x_kernel<<<BATCH, 256>>>(ability_ids, move_ids, ability_emb, move_emb, h0);
    gemm_lstm_kernel<<<dim3(NGATES / 128, BATCH / 128), 128, GEMM_SMEM>>>(c0, h1o, c1o);
    head_kernel<<<BATCH / 16, 256, HEAD_SMEM>>>(h1o, mask, W1, b1, W2, b2, Wa, ba, probs);

    (void)in_sizes; (void)n_in;
}

// round 15
// speedup vs baseline: 1.0120x; 1.0120x over previous
#include <cuda_runtime.h>
#include <cuda_bf16.h>
#include <cstdint>
#include <math.h>

// ---------------- sizes ----------------
#define BATCH   4096
#define EDIM    128
#define KIH     7808
#define KDIM    7936            // KIH + 128 (h0 folded in)
#define NGATES  512
#define LHID    128
#define HDIM    64
#define NCHUNK  (KDIM/32)       // 248 k-chunks of 32 floats

// ---------------- device scratch (static: no allocs allowed) ----------------
__device__ __align__(1024) float g_x[(size_t)BATCH * KDIM];    // ~130 MB
__device__ __align__(1024) float g_W[(size_t)NGATES * KDIM];   // ~16 MB
__device__ float g_bias[NGATES];
__device__ float g_h1[(size_t)BATCH * LHID];                   // fallback homes
__device__ float g_c1[(size_t)BATCH * LHID];

// ---------------- helpers ----------------
__device__ __forceinline__ uint32_t smem_to_u32(const void* p) {
    uint32_t a;
    asm("{ .reg .u64 t; cvta.to.shared.u64 t, %1; cvt.u32.u64 %0, t; }" : "=r"(a) : "l"(p));
    return a;
}
__device__ __forceinline__ float tf32r(float x) {
    uint32_t u;
    asm("cvt.rna.tf32.f32 %0, %1;" : "=r"(u) : "f"(x));
    return __uint_as_float(u);
}
#define CP_ASYNC16(sm_u32, gptr) \
    asm volatile("cp.async.cg.shared.global [%0], [%1], 16;" :: "r"(sm_u32), "l"(gptr))
#define CP_COMMIT() asm volatile("cp.async.commit_group;")
#define CP_WAIT(n)  asm volatile("cp.async.wait_group %0;" :: "n"(n))

#define LDMX4(r0, r1, r2, r3, addr) \
    asm volatile("ldmatrix.sync.aligned.m8n8.x4.shared.b16 {%0,%1,%2,%3}, [%4];" \
                 : "=r"(r0), "=r"(r1), "=r"(r2), "=r"(r3) : "r"(addr))

#define MMA_TF32(d, a, b0, b1) \
    asm volatile("mma.sync.aligned.m16n8k8.row.col.f32.tf32.tf32.f32 " \
                 "{%0,%1,%2,%3}, {%4,%5,%6,%7}, {%8,%9}, {%0,%1,%2,%3};" \
                 : "+f"((d)[0]), "+f"((d)[1]), "+f"((d)[2]), "+f"((d)[3]) \
                 : "r"((a)[0]), "r"((a)[1]), "r"((a)[2]), "r"((a)[3]), \
                   "r"(b0), "r"(b1))

// =====================================================================
// K1: permute + pack W = [Wih | Whh], row p = 4h+gate (gate order i,f,g,o)
// =====================================================================
__global__ void prep_w_kernel(const float* __restrict__ Wih, const float* __restrict__ Whh,
                              const float* __restrict__ bih, const float* __restrict__ bhh) {
    const int p = blockIdx.y;
    const int col = blockIdx.x * 256 + threadIdx.x;   // 0..7935
    const int h = p >> 2, gate = p & 3;
    const int orig = gate * LHID + h;
    float v = (col < KIH) ? Wih[(size_t)orig * KIH + col]
                          : Whh[(size_t)orig * LHID + (col - KIH)];
    g_W[(size_t)p * KDIM + col] = tf32r(v);
    if (blockIdx.x == 0 && threadIdx.x == 0)
        g_bias[p] = bih[orig] + bhh[orig];
}

// =====================================================================
// K2: numerical projection -> g_x cols [7680,7808), num_W cached in smem
// =====================================================================
#define NUM_SMEM ((32*84 + 128*85) * 4)
__global__ void num_kernel(const float* __restrict__ numerical,
                           const float* __restrict__ num_W, const float* __restrict__ num_b) {
    extern __shared__ float sm[];
    float* snum = sm;                  // [32][84]
    float* sW = sm + 32 * 84;          // [128][85] padded
    const int t = threadIdx.x;
    const int b0 = blockIdx.x * 32;
    for (int i = t; i < 32 * 84; i += 128)
        snum[i] = numerical[(size_t)b0 * 84 + i];
    for (int i = t; i < 128 * 84; i += 128) {
        int e = i / 84, k = i - e * 84;
        sW[e * 85 + k] = num_W[i];
    }
    __syncthreads();
    const int e = t; // 0..127
    float bb = num_b[e];
    for (int r = 0; r < 32; r++) {
        float acc = bb;
        #pragma unroll 4
        for (int k = 0; k < 84; k++)
            acc += snum[r * 84 + k] * sW[e * 85 + k];
        g_x[(size_t)(b0 + r) * KDIM + 7680 + e] = tf32r(acc);
    }
}

// =====================================================================
// K3: gather-build x rows: [12*128 ab | 48*128 mv | 128 num(skip) | 128 h0]
// =====================================================================
__global__ void build_x_kernel(const int* __restrict__ aid_g, const int* __restrict__ mid_g,
                               const float* __restrict__ aemb, const float* __restrict__ memb,
                               const float* __restrict__ h0) {
    const int b = blockIdx.x;
    const int* aid = aid_g + b * 12;
    const int* mid = mid_g + b * 48;
    float4* dst = ((float4*)g_x) + (size_t)b * (KDIM / 4);
    for (int c = threadIdx.x; c < 1952; c += blockDim.x) {
        const float4* src;
        int dc;
        if (c < 384) {                       // ability: 12 segs x 32 f4
            int j = c >> 5, e4 = c & 31;
            src = ((const float4*)(aemb + (size_t)aid[j] * EDIM)) + e4;
            dc = c;
        } else if (c < 1920) {               // moves: 48 segs x 32 f4
            int cm = c - 384;
            int j = cm >> 5, e4 = cm & 31;
            src = ((const float4*)(memb + (size_t)mid[j] * EDIM)) + e4;
            dc = c;
        } else {                             // h0 -> cols [7808,7936)
            int e4 = c - 1920;
            src = ((const float4*)(h0 + (size_t)b * LHID)) + e4;
            dc = c + 32;                     // skip num region (32 f4)
        }
        float4 v = *src;
        v.x = tf32r(v.x); v.y = tf32r(v.y); v.z = tf32r(v.z); v.w = tf32r(v.w);
        dst[dc] = v;
    }
}

// =====================================================================
// K4: tf32 mma.sync GEMM (4096x512x7936) + fused LSTM cell epilogue
// grid (4 nt, 32 mt), 256 threads = 8 warps, each warp a 64x32 quadrant
// (warpM = (wid>>2)*64, warpN = (wid&3)*32).
// 3-stage cp.async pipeline. Smem row pitch 36 floats (144B): ldmatrix
// rows land in disjoint bank groups (36r mod 32 = 4r) -> conflict-free.
// =====================================================================
#define APITCH_F 36
#define APITCH_B 144
#define ATILE_B  (128 * APITCH_B)          // 18432 bytes per operand tile
#define STAGE_B  (2 * ATILE_B)             // 36864: A tile then B tile
#define NSTG     3
#define GEMM_SMEM (NSTG * STAGE_B)         // 110592 bytes
#define GPITCH_F 132                       // gates staging pitch

__device__ __forceinline__ void load_stage(int s, int kc, int mt, int nt,
                                           int tid, uint32_t sbase) {
    const float* ga = g_x + (size_t)(mt * 128) * KDIM + kc * 32;
    const float* gb = g_W + (size_t)(nt * 128) * KDIM + kc * 32;
    const uint32_t sa = sbase + s * STAGE_B;
    const uint32_t sb2 = sa + ATILE_B;
    #pragma unroll
    for (int i = 0; i < 4; i++) {
        int g = tid + i * 256;             // 0..1023 granules of 16B
        int row = g >> 3, c = g & 7;
        CP_ASYNC16(sa  + row * APITCH_B + c * 16, ga + (size_t)row * KDIM + c * 4);
        CP_ASYNC16(sb2 + row * APITCH_B + c * 16, gb + (size_t)row * KDIM + c * 4);
    }
    CP_COMMIT();
}

__global__ void __launch_bounds__(256, 1)
gemm_lstm_kernel(const float* __restrict__ c0,
                 float* __restrict__ out_h1, float* __restrict__ out_c1) {
    extern __shared__ char smem[];
    const uint32_t sbase = smem_to_u32(smem);
    const int tid = threadIdx.x, lane = tid & 31, wid = tid >> 5;
    const int nt = blockIdx.x, mt = blockIdx.y;
    const int warpM = (wid >> 2) * 64;     // 0 or 64
    const int warpN = (wid & 3) * 32;      // 0,32,64,96

    float acc[4][4][4];
    #pragma unroll
    for (int i = 0; i < 4; i++)
        #pragma unroll
        for (int n = 0; n < 4; n++)
            #pragma unroll
            for (int q = 0; q < 4; q++) acc[i][n][q] = 0.0f;

    // per-thread ldmatrix base (within A tile): sub-matrix role of this lane
    const int sub = lane >> 3, rr = lane & 7;
    const uint32_t a_base_off =
        (uint32_t)(warpM + ((sub & 1) << 3) + rr) * APITCH_B + ((sub >> 1) << 4);
    // per-thread B base (float index within B tile)
    const int b_base = (warpN + (lane >> 2)) * APITCH_F + (lane & 3);

    load_stage(0, 0, mt, nt, tid, sbase);
    load_stage(1, 1, mt, nt, tid, sbase);

    for (int kc = 0; kc < NCHUNK; kc++) {
        CP_WAIT(1);
        __syncthreads();
        if (kc + 2 < NCHUNK)
            load_stage((kc + 2) % NSTG, kc + 2, mt, nt, tid, sbase);

        const int st = kc % NSTG;
        const uint32_t a0 = sbase + st * STAGE_B + a_base_off;
        const float* bs = (const float*)(smem + st * STAGE_B + ATILE_B) + b_base;

        #pragma unroll
        for (int j = 0; j < 4; j++) {      // k-steps of 8 within the 32-chunk
            uint32_t af[4][4];
            #pragma unroll
            for (int i = 0; i < 4; i++)
                LDMX4(af[i][0], af[i][1], af[i][2], af[i][3],
                      a0 + i * 16 * APITCH_B + j * 32);
            uint32_t bf0[4], bf1[4];
            #pragma unroll
            for (int n = 0; n < 4; n++) {
                bf0[n] = __float_as_uint(bs[n * 8 * APITCH_F + j * 8]);
                bf1[n] = __float_as_uint(bs[n * 8 * APITCH_F + j * 8 + 4]);
            }
            #pragma unroll
            for (int i = 0; i < 4; i++)
                #pragma unroll
                for (int n = 0; n < 4; n++)
                    MMA_TF32(acc[i][n], af[i], bf0[n], bf1[n]);
        }
    }
    CP_WAIT(0);
    __syncthreads();

    // ---- stage gates through smem so each thread gets full i,f,g,o ----
    float* sg = (float*)smem;              // [128][GPITCH_F]
    {
        const int r0 = lane >> 2, c0i = 2 * (lane & 3);
        #pragma unroll
        for (int i = 0; i < 4; i++)
            #pragma unroll
            for (int n = 0; n < 4; n++) {
                const int row = warpM + 16 * i + r0;
                const int col = warpN + 8 * n + c0i;
                sg[row * GPITCH_F + col]           = acc[i][n][0];
                sg[row * GPITCH_F + col + 1]       = acc[i][n][1];
                sg[(row + 8) * GPITCH_F + col]     = acc[i][n][2];
                sg[(row + 8) * GPITCH_F + col + 1] = acc[i][n][3];
            }
    }
    __syncthreads();

    // ---- fused LSTM cell: 2 threads per batch row, 16 h-units each ----
    {
        const int row = tid >> 1;          // 0..127
        const int half = tid & 1;          // 0 or 1
        const int m = mt * 128 + row;
        const float* c0row = c0 + (size_t)m * LHID;
        float* h1row = out_h1 + (size_t)m * LHID;
        float* c1row = out_c1 + (size_t)m * LHID;
        const float* grow = sg + row * GPITCH_F;
        #pragma unroll 4
        for (int q = 0; q < 16; q++) {
            const int hl = half * 16 + q;
            const int pb = nt * 128 + 4 * hl;
            float gi = grow[4 * hl + 0] + g_bias[pb + 0];
            float gf = grow[4 * hl + 1] + g_bias[pb + 1];
            float gg = grow[4 * hl + 2] + g_bias[pb + 2];
            float go = grow[4 * hl + 3] + g_bias[pb + 3];
            float iv = 1.0f / (1.0f + expf(-gi));
            float fv = 1.0f / (1.0f + expf(-gf));
            float gv = tanhf(gg);
            float ov = 1.0f / (1.0f + expf(-go));
            const int h = nt * 32 + hl;
            float c1 = fv * c0row[h] + iv * gv;
            float h1 = ov * tanhf(c1);
            h1row[h] = h1;
            c1row[h] = c1;
        }
    }
}

// =====================================================================
// K5: MLP head + softmax + masked renorm. 16 rows/block, 256 threads.
// =====================================================================
#define W1S 132
#define W2S 68
#define WAS 132
#define H1S 132
#define FTS 132
#define OW1 0
#define OW2 (OW1 + 64 * W1S)
#define OWA (OW2 + 128 * W2S)
#define OB1 (OWA + 9 * WAS)
#define OB2 (OB1 + 64)
#define OBA (OB2 + 128)
#define OH1 (OBA + 12)
#define OZ1 (OH1 + 16 * H1S)
#define OFT (OZ1 + 16 * 64)
#define HEAD_FLOATS (OFT + 16 * FTS)
#define HEAD_SMEM (HEAD_FLOATS * 4)

__global__ void head_kernel(const float* __restrict__ h1g, const float* __restrict__ mask,
                            const float* __restrict__ W1, const float* __restrict__ b1,
                            const float* __restrict__ W2, const float* __restrict__ b2,
                            const float* __restrict__ Wa, const float* __restrict__ ba,
                            float* __restrict__ probs) {
    extern __shared__ float sm[];
    const int t = threadIdx.x;
    const int b0 = blockIdx.x * 16;

    for (int i = t; i < 64 * 128; i += 256) { int r = i >> 7, k = i & 127; sm[OW1 + r * W1S + k] = W1[i]; }
    for (int i = t; i < 128 * 64; i += 256) { int r = i >> 6, k = i & 63;  sm[OW2 + r * W2S + k] = W2[i]; }
    for (int i = t; i < 9 * 128;  i += 256) { int r = i >> 7, k = i & 127; sm[OWA + r * WAS + k] = Wa[i]; }
    if (t < 64)  sm[OB1 + t] = b1[t];
    if (t < 128) sm[OB2 + t] = b2[t];
    if (t < 9)   sm[OBA + t] = ba[t];
    for (int i = t; i < 16 * 128; i += 256) { int r = i >> 7, k = i & 127; sm[OH1 + r * H1S + k] = h1g[(size_t)(b0 + r) * LHID + k]; }
    __syncthreads();

    for (int oi = t; oi < 16 * 64; oi += 256) {
        int r = oi >> 6, j = oi & 63;
        float acc = sm[OB1 + j];
        #pragma unroll 8
        for (int k = 0; k < 32; k++) {
            float4 a = *(const float4*)&sm[OH1 + r * H1S + 4 * k];
            float4 w = *(const float4*)&sm[OW1 + j * W1S + 4 * k];
            acc += a.x * w.x + a.y * w.y + a.z * w.z + a.w * w.w;
        }
        sm[OZ1 + r * 64 + j] = fmaxf(acc, 0.0f);
    }
    __syncthreads();

    for (int oi = t; oi < 16 * 128; oi += 256) {
        int r = oi >> 7, e = oi & 127;
        float acc = sm[OB2 + e];
        #pragma unroll 8
        for (int k = 0; k < 16; k++) {
            float4 a = *(const float4*)&sm[OZ1 + r * 64 + 4 * k];
            float4 w = *(const float4*)&sm[OW2 + e * W2S + 4 * k];
            acc += a.x * w.x + a.y * w.y + a.z * w.z + a.w * w.w;
        }
        sm[OFT + r * FTS + e] = acc;
    }
    __syncthreads();

    if (t < 16) {
        const int r = t, b = b0 + r;
        float lg[9];
        #pragma unroll
        for (int j = 0; j < 9; j++) {
            float acc = sm[OBA + j];
            #pragma unroll 8
            for (int k = 0; k < 32; k++) {
                float4 a = *(const float4*)&sm[OFT + r * FTS + 4 * k];
                float4 w = *(const float4*)&sm[OWA + j * WAS + 4 * k];
                acc += a.x * w.x + a.y * w.y + a.z * w.z + a.w * w.w;
            }
            lg[j] = acc;
        }
        float mx = lg[0];
        #pragma unroll
        for (int j = 1; j < 9; j++) mx = fmaxf(mx, lg[j]);
        float ex[9], se = 0.0f;
        #pragma unroll
        for (int j = 0; j < 9; j++) { ex[j] = expf(lg[j] - mx); se += ex[j]; }
        float inv = 1.0f / se;
        float p[9], mk[9], ms = 0.0f;
        #pragma unroll
        for (int j = 0; j < 9; j++) {
            p[j] = ex[j] * inv;
            mk[j] = mask[(size_t)b * 9 + j];
            ms += p[j] * mk[j];
        }
        if (ms > 0.0f) {
            float mi = 1.0f / ms;
            #pragma unroll
            for (int j = 0; j < 9; j++) probs[(size_t)b * 9 + j] = p[j] * mk[j] * mi;
        } else {
            #pragma unroll
            for (int j = 0; j < 9; j++) probs[(size_t)b * 9 + j] = p[j];
        }
    }
}

// =====================================================================
// launcher
// =====================================================================
extern "C" void kernel_launch(void* const* d_in, const int* in_sizes, int n_in,
                              void* d_out, int out_size) {
    const int*   ability_ids = (const int*)d_in[0];
    const int*   move_ids    = (const int*)d_in[1];
    const float* numerical   = (const float*)d_in[2];
    const float* mask        = (const float*)d_in[3];
    const float* h0          = (const float*)d_in[4];
    const float* c0          = (const float*)d_in[5];
    const float* ability_emb = (const float*)d_in[6];
    const float* move_emb    = (const float*)d_in[7];
    const float* num_W       = (const float*)d_in[8];
    const float* num_b       = (const float*)d_in[9];
    const float* Wih         = (const float*)d_in[10];
    const float* Whh         = (const float*)d_in[11];
    const float* bih         = (const float*)d_in[12];
    const float* bhh         = (const float*)d_in[13];
    const float* W1          = (const float*)d_in[14];
    const float* b1          = (const float*)d_in[15];
    const float* W2          = (const float*)d_in[16];
    const float* b2          = (const float*)d_in[17];
    const float* Wa          = (const float*)d_in[18];
    const float* ba          = (const float*)d_in[19];

    float* out   = (float*)d_out;
    float* probs = out;

    // defensive output routing: tuple (probs, h1, c1) expected; fall back to
    // scratch for h1/c1 if d_out is smaller than the full tuple.
    const long long full = (long long)BATCH * 9 + 2LL * BATCH * LHID;
    void *ph1s = nullptr, *pc1s = nullptr;
    cudaGetSymbolAddress(&ph1s, g_h1);
    cudaGetSymbolAddress(&pc1s, g_c1);
    float* h1o = (out_size >= full) ? out + (size_t)BATCH * 9 : (float*)ph1s;
    float* c1o = (out_size >= full) ? h1o + (size_t)BATCH * LHID : (float*)pc1s;

    cudaFuncSetAttribute(gemm_lstm_kernel, cudaFuncAttributeMaxDynamicSharedMemorySize, GEMM_SMEM);
    cudaFuncSetAttribute(num_kernel,       cudaFuncAttributeMaxDynamicSharedMemorySize, NUM_SMEM);
    cudaFuncSetAttribute(head_kernel,      cudaFuncAttributeMaxDynamicSharedMemorySize, HEAD_SMEM);

    prep_w_kernel<<<dim3(KDIM / 256, NGATES), 256>>>(Wih, Whh, bih, bhh);
    num_kernel<<<BATCH / 32, 128, NUM_SMEM>>>(numerical, num_W, num_b);
    build_x_kernel<<<BATCH, 256>>>(ability_ids, move_ids, ability_emb, move_emb, h0);
    gemm_lstm_kernel<<<dim3(NGATES / 128, BATCH / 128), 256, GEMM_SMEM>>>(c0, h1o, c1o);
    head_kernel<<<BATCH / 16, 256, HEAD_SMEM>>>(h1o, mask, W1, b1, W2, b2, Wa, ba, probs);

    (void)in_sizes; (void)n_in;
}